// round 6
// baseline (speedup 1.0000x reference)
#include <cuda_runtime.h>
#include <cstdint>
#include <math.h>

// ---------------- problem constants ----------------
#define H      1024
#define E      1024
#define E2     2048
#define NEXP   16
#define NTOK   1024
#define NASSIGN 2048
#define ALPHA  1.702f
#define LIMIT  7.0f

// smem: two stages of (A tile 16KB + B tile 16KB)
#define STAGE_SZ 32768
#define B_OFF    16384
#define SMEM_TOTAL (2 * STAGE_SZ)   // 64KB

// ---------------- device scratch ----------------
__device__ int   g_counts[NEXP];
__device__ int   g_off[NEXP];
__device__ int   g_fill[NEXP];
__device__ int   g_te[NTOK * 2];
__device__ float g_tw[NTOK * 2];
__device__ int   g_slot[NTOK * 2];
__device__ int   g_tok[NASSIGN];
__device__ float g_gated[(size_t)NASSIGN * E];   // 8 MB
__device__ float g_y[(size_t)NASSIGN * H];       // 8 MB

// ---------------- PTX helpers ----------------
__device__ __forceinline__ uint32_t smem_u32(const void* p) {
    uint32_t a;
    asm("{ .reg .u64 t; cvta.to.shared.u64 t, %1; cvt.u32.u64 %0, t; }" : "=r"(a) : "l"(p));
    return a;
}

__device__ __forceinline__ void ldm_x4(uint32_t (&r)[4], uint32_t addr) {
    asm volatile("ldmatrix.sync.aligned.m8n8.x4.shared.b16 {%0,%1,%2,%3}, [%4];"
                 : "=r"(r[0]), "=r"(r[1]), "=r"(r[2]), "=r"(r[3]) : "r"(addr));
}

__device__ __forceinline__ void mma_bf16(float (&d)[4], const uint32_t (&a)[4],
                                         uint32_t b0, uint32_t b1) {
    asm volatile("mma.sync.aligned.m16n8k16.row.col.f32.bf16.bf16.f32 "
                 "{%0,%1,%2,%3}, {%4,%5,%6,%7}, {%8,%9}, {%0,%1,%2,%3};"
                 : "+f"(d[0]), "+f"(d[1]), "+f"(d[2]), "+f"(d[3])
                 : "r"(a[0]), "r"(a[1]), "r"(a[2]), "r"(a[3]), "r"(b0), "r"(b1));
}

#define STS128(a0, a1, a2, a3, addr) \
    asm volatile("st.shared.v4.b32 [%0], {%1, %2, %3, %4};" \
                 :: "r"(addr), "r"(a0), "r"(a1), "r"(a2), "r"(a3) : "memory")

// row has 8 chunks of 16B: [hi: 0-3 | lo: 4-7]; Swizzle<3,4,3>
__device__ __forceinline__ uint32_t swz_off(int row, int chunk) {
    return (uint32_t)(row * 128 + ((chunk ^ (row & 7)) << 4));
}

// pack (f0,f1) -> bf16x2 hi (f0 in low half) + bf16x2 residual lo
__device__ __forceinline__ void split_pack2(float f0, float f1, uint32_t& hi, uint32_t& lo) {
    uint32_t h;
    asm("cvt.rn.bf16x2.f32 %0, %1, %2;" : "=r"(h) : "f"(f1), "f"(f0));
    float l0 = f0 - __uint_as_float(h << 16);
    float l1 = f1 - __uint_as_float(h & 0xffff0000u);
    uint32_t l;
    asm("cvt.rn.bf16x2.f32 %0, %1, %2;" : "=r"(l) : "f"(l1), "f"(l0));
    hi = h; lo = l;
}

// ---------------- router path ----------------
__global__ void init_kernel() {
    if (threadIdx.x < NEXP) g_counts[threadIdx.x] = 0;
}

__global__ void router_kernel(const float* __restrict__ x,
                              const float* __restrict__ Wg,
                              const float* __restrict__ bg) {
    int t = blockIdx.x * blockDim.y + threadIdx.y;
    int lane = threadIdx.x;
    if (t >= NTOK) return;
    const float* xr = x + (size_t)t * H;
    float logits[NEXP];
#pragma unroll
    for (int e = 0; e < NEXP; e++) {
        const float* wr = Wg + e * H;
        float s = 0.0f;
        for (int h = lane; h < H; h += 32) s += xr[h] * wr[h];
#pragma unroll
        for (int off = 16; off > 0; off >>= 1) s += __shfl_xor_sync(0xffffffffu, s, off);
        logits[e] = s + bg[e];
    }
    if (lane == 0) {
        int i0 = 0; float v0 = logits[0];
#pragma unroll
        for (int e = 1; e < NEXP; e++) if (logits[e] > v0) { v0 = logits[e]; i0 = e; }
        int i1 = -1; float v1 = -INFINITY;
#pragma unroll
        for (int e = 0; e < NEXP; e++) if (e != i0 && logits[e] > v1) { v1 = logits[e]; i1 = e; }
        float r  = expf(v1 - v0);
        float w0 = 1.0f / (1.0f + r);
        g_te[t * 2 + 0] = i0;  g_tw[t * 2 + 0] = w0;
        g_te[t * 2 + 1] = i1;  g_tw[t * 2 + 1] = r * w0;
        atomicAdd(&g_counts[i0], 1);
        atomicAdd(&g_counts[i1], 1);
    }
}

// merged scan + fill: ONE block of 1024 threads (keeps gemm1 as 4th launch)
__global__ void scanfill_kernel() {
    const int t = threadIdx.x;
    if (t == 0) {
        int acc = 0;
#pragma unroll
        for (int e = 0; e < NEXP; e++) { g_off[e] = acc; acc += g_counts[e]; g_fill[e] = 0; }
    }
    __syncthreads();
#pragma unroll
    for (int k = 0; k < 2; k++) {
        int e = g_te[t * 2 + k];
        int pos = atomicAdd(&g_fill[e], 1);
        int idx = g_off[e] + pos;
        g_tok[idx] = t;
        g_slot[t * 2 + k] = idx;
    }
}

// ---------------- shared mma.sync mainloop (128x128 tile) ----------------
// 3-term bf16 emulation with SPLIT accumulators:
//   acch = Ah*Bh ; accm = Ah*Bl + Al*Bh   (shorter RAW chains, 2x mma ILP)
__device__ __forceinline__ void gemm_tile(const float4* __restrict__ arow,
                                          const float*  __restrict__ bcol, int ldb,
                                          char* smem,
                                          float acch[2][8][4], float accm[2][8][4],
                                          int kiters) {
    const int tid  = threadIdx.x;
    const int lane = tid & 31;
    const int w    = tid >> 5;
    const int wm   = w & 3;
    const int wn   = w >> 2;
    const int lrow = tid & 127;
    const int half = tid >> 7;        // which 16 of the 32-k chunk this thread loads

    const uint32_t sb = smem_u32(smem);

    const uint32_t sH0 = swz_off(lrow, half * 2);
    const uint32_t sH1 = swz_off(lrow, half * 2 + 1);
    const uint32_t sL0 = swz_off(lrow, 4 + half * 2);
    const uint32_t sL1 = swz_off(lrow, 5 + half * 2);

    const int rA0 = wm * 32 + (lane & 15);
    const int rB0 = wn * 64 + (lane & 7) + ((lane >> 4) << 3);
    const int bkc = (lane >> 3) & 1;
    const int akc = lane >> 4;

    float4 pa[4];
    float  pb[16];

    auto load = [&](int it) {
        const int kb = it * 32 + half * 16;
        if (arow) {
#pragma unroll
            for (int i = 0; i < 4; i++) pa[i] = arow[(kb >> 2) + i];
        } else {
#pragma unroll
            for (int i = 0; i < 4; i++) pa[i] = make_float4(0.f, 0.f, 0.f, 0.f);
        }
#pragma unroll
        for (int j = 0; j < 16; j++) pb[j] = bcol[(size_t)(kb + j) * ldb];
    };

    auto sts = [&](uint32_t stg) {
        uint32_t h[8], l[8];
        split_pack2(pa[0].x, pa[0].y, h[0], l[0]);
        split_pack2(pa[0].z, pa[0].w, h[1], l[1]);
        split_pack2(pa[1].x, pa[1].y, h[2], l[2]);
        split_pack2(pa[1].z, pa[1].w, h[3], l[3]);
        split_pack2(pa[2].x, pa[2].y, h[4], l[4]);
        split_pack2(pa[2].z, pa[2].w, h[5], l[5]);
        split_pack2(pa[3].x, pa[3].y, h[6], l[6]);
        split_pack2(pa[3].z, pa[3].w, h[7], l[7]);
        STS128(h[0], h[1], h[2], h[3], stg + sH0);
        STS128(h[4], h[5], h[6], h[7], stg + sH1);
        STS128(l[0], l[1], l[2], l[3], stg + sL0);
        STS128(l[4], l[5], l[6], l[7], stg + sL1);
#pragma unroll
        for (int p = 0; p < 8; p++) split_pack2(pb[2 * p], pb[2 * p + 1], h[p], l[p]);
        STS128(h[0], h[1], h[2], h[3], stg + B_OFF + sH0);
        STS128(h[4], h[5], h[6], h[7], stg + B_OFF + sH1);
        STS128(l[0], l[1], l[2], l[3], stg + B_OFF + sL0);
        STS128(l[4], l[5], l[6], l[7], stg + B_OFF + sL1);
    };

    auto compute = [&](uint32_t stg) {
#pragma unroll
        for (int s = 0; s < 2; s++) {
            uint32_t ah[2][4], al[2][4];
#pragma unroll
            for (int t = 0; t < 2; t++) {
                int row = rA0 + t * 16;
                int ch  = 2 * s + akc;
                ldm_x4(ah[t], stg + swz_off(row, ch));
                ldm_x4(al[t], stg + swz_off(row, ch + 4));
            }
#pragma unroll
            for (int ug = 0; ug < 4; ug++) {
                int row = rB0 + ug * 16;
                int ch  = 2 * s + bkc;
                uint32_t bh[4], bl[4];
                ldm_x4(bh, stg + B_OFF + swz_off(row, ch));
                ldm_x4(bl, stg + B_OFF + swz_off(row, ch + 4));
#pragma unroll
                for (int t = 0; t < 2; t++) {
#pragma unroll
                    for (int uu = 0; uu < 2; uu++) {
                        mma_bf16(acch[t][ug * 2 + uu], ah[t], bh[uu * 2], bh[uu * 2 + 1]);
                        mma_bf16(accm[t][ug * 2 + uu], ah[t], bl[uu * 2], bl[uu * 2 + 1]);
                        mma_bf16(accm[t][ug * 2 + uu], al[t], bh[uu * 2], bh[uu * 2 + 1]);
                    }
                }
            }
        }
    };

    load(0);
    sts(sb);
    __syncthreads();
    for (int it = 0; it < kiters; it++) {
        const uint32_t cur = sb + (uint32_t)(it & 1) * STAGE_SZ;
        const uint32_t nxt = sb + (uint32_t)((it + 1) & 1) * STAGE_SZ;
        if (it + 1 < kiters) load(it + 1);
        compute(cur);
        if (it + 1 < kiters) sts(nxt);
        __syncthreads();
    }
}

// ---------------- GEMM1: X @ Wgu -> clamp/GLU -> g_gated ----------------
__global__ __launch_bounds__(256, 1)
void gemm1_kernel(const float* __restrict__ x,
                  const float* __restrict__ Wgu,
                  const float* __restrict__ bgu) {
    const int e  = blockIdx.z;
    const int ne = g_counts[e];
    const int m0 = blockIdx.y * 128;
    if (m0 >= ne) return;
    const int n0   = blockIdx.x * 128;
    const int base = g_off[e];

    extern __shared__ char smem[];
    const int tid = threadIdx.x, lane = tid & 31, w = tid >> 5;
    const int wm = w & 3, wn = w >> 2;
    const int lrow = tid & 127;

    const int gmL = m0 + lrow;
    const float4* arow = (gmL < ne) ? (const float4*)(x + (size_t)g_tok[base + gmL] * H)
                                    : nullptr;
    const float* bcol = Wgu + (size_t)e * H * E2 + n0 + lrow;

    float acch[2][8][4] = {};
    float accm[2][8][4] = {};
    gemm_tile(arow, bcol, E2, smem, acch, accm, H / 32);

#pragma unroll
    for (int t = 0; t < 2; t++) {
        const int r = wm * 32 + t * 16 + (lane >> 2);
#pragma unroll
        for (int u = 0; u < 8; u++) {
            const int gcol = n0 + wn * 64 + u * 8 + (lane & 3) * 2;
            const float b0 = bgu[e * E2 + gcol];
            const float b1 = bgu[e * E2 + gcol + 1];
#pragma unroll
            for (int hh = 0; hh < 2; hh++) {
                const int gm = m0 + r + hh * 8;
                if (gm < ne) {
                    float gate = acch[t][u][hh * 2]     + accm[t][u][hh * 2]     + b0;
                    float up   = acch[t][u][hh * 2 + 1] + accm[t][u][hh * 2 + 1] + b1;
                    gate = fminf(gate, LIMIT);
                    up   = fminf(fmaxf(up, -LIMIT), LIMIT);
                    float glu = gate / (1.0f + __expf(-ALPHA * gate));
                    g_gated[(size_t)(base + gm) * E + (gcol >> 1)] = (up + 1.0f) * glu;
                }
            }
        }
    }
}

// ---------------- GEMM2: gated @ Wd -> per-assignment rows g_y ----------------
__global__ __launch_bounds__(256, 1)
void gemm2_kernel(const float* __restrict__ Wd,
                  const float* __restrict__ bd) {
    const int e  = blockIdx.z;
    const int ne = g_counts[e];
    const int m0 = blockIdx.y * 128;
    if (m0 >= ne) return;
    const int n0   = blockIdx.x * 128;
    const int base = g_off[e];

    extern __shared__ char smem[];
    const int tid = threadIdx.x, lane = tid & 31, w = tid >> 5;
    const int wm = w & 3, wn = w >> 2;
    const int lrow = tid & 127;

    const int gmL = m0 + lrow;
    const float4* arow = (gmL < ne) ? (const float4*)(g_gated + (size_t)(base + gmL) * E)
                                    : nullptr;
    const float* bcol = Wd + (size_t)e * E * H + n0 + lrow;

    float acch[2][8][4] = {};
    float accm[2][8][4] = {};
    gemm_tile(arow, bcol, H, smem, acch, accm, E / 32);

#pragma unroll
    for (int t = 0; t < 2; t++) {
        const int r = wm * 32 + t * 16 + (lane >> 2);
#pragma unroll
        for (int u = 0; u < 8; u++) {
            const int col = n0 + wn * 64 + u * 8 + (lane & 3) * 2;
            const float b0 = bd[e * H + col];
            const float b1 = bd[e * H + col + 1];
#pragma unroll
            for (int hh = 0; hh < 2; hh++) {
                const int gm = m0 + r + hh * 8;
                if (gm < ne) {
                    float2 v = make_float2(acch[t][u][hh * 2]     + accm[t][u][hh * 2]     + b0,
                                           acch[t][u][hh * 2 + 1] + accm[t][u][hh * 2 + 1] + b1);
                    *(float2*)&g_y[(size_t)(base + gm) * H + col] = v;
                }
            }
        }
    }
}

// ---------------- combine: out[t] = w0*y[slot0] + w1*y[slot1] ----------------
__global__ void combine_kernel(float* __restrict__ out) {
    const int i = blockIdx.x * 256 + threadIdx.x;   // over NTOK*H/4
    const int t = i >> 8;
    const int c = i & 255;
    const int s0 = g_slot[t * 2], s1 = g_slot[t * 2 + 1];
    const float w0 = g_tw[t * 2], w1 = g_tw[t * 2 + 1];
    const float4 a = ((const float4*)(g_y + (size_t)s0 * H))[c];
    const float4 b = ((const float4*)(g_y + (size_t)s1 * H))[c];
    float4 o;
    o.x = w0 * a.x + w1 * b.x;
    o.y = w0 * a.y + w1 * b.y;
    o.z = w0 * a.z + w1 * b.z;
    o.w = w0 * a.w + w1 * b.w;
    ((float4*)out)[i] = o;
}

// ---------------- launch ----------------
extern "C" void kernel_launch(void* const* d_in, const int* in_sizes, int n_in,
                              void* d_out, int out_size) {
    (void)in_sizes; (void)n_in; (void)out_size;
    const float* x   = (const float*)d_in[0];
    const float* Wg  = (const float*)d_in[1];
    const float* bg  = (const float*)d_in[2];
    const float* Wgu = (const float*)d_in[3];
    const float* bgu = (const float*)d_in[4];
    const float* Wd  = (const float*)d_in[5];
    const float* bd  = (const float*)d_in[6];
    float* out = (float*)d_out;

    static bool attr_set = false;
    if (!attr_set) {
        cudaFuncSetAttribute(gemm1_kernel, cudaFuncAttributeMaxDynamicSharedMemorySize, SMEM_TOTAL);
        cudaFuncSetAttribute(gemm2_kernel, cudaFuncAttributeMaxDynamicSharedMemorySize, SMEM_TOTAL);
        attr_set = true;
    }

    // gemm1 is deliberately the 4th launch: ncu's fixed skip-count profiles it.
    init_kernel<<<1, 32>>>();
    router_kernel<<<NTOK / 8, dim3(32, 8)>>>(x, Wg, bg);
    scanfill_kernel<<<1, 1024>>>();
    gemm1_kernel<<<dim3(E2 / 128, 8, NEXP), 256, SMEM_TOTAL>>>(x, Wgu, bgu);
    gemm2_kernel<<<dim3(H / 128, 8, NEXP), 256, SMEM_TOTAL>>>(Wd, bd);
    combine_kernel<<<NTOK * H / 4 / 256, 256>>>(out);
}

// round 7
// speedup vs baseline: 1.3264x; 1.3264x over previous
#include <cuda_runtime.h>
#include <cstdint>
#include <math.h>

// ---------------- problem constants ----------------
#define H      1024
#define E      1024
#define E2     2048
#define NEXP   16
#define NTOK   1024
#define NASSIGN 2048
#define ALPHA  1.702f
#define LIMIT  7.0f

// smem: THREE stages of (A tile 16KB + B tile 16KB)
#define STAGE_SZ 32768
#define B_OFF    16384
#define SMEM_TOTAL (3 * STAGE_SZ)   // 96KB

// ---------------- device scratch ----------------
__device__ int   g_counts[NEXP];
__device__ int   g_off[NEXP];
__device__ int   g_fill[NEXP];
__device__ int   g_te[NTOK * 2];
__device__ float g_tw[NTOK * 2];
__device__ int   g_slot[NTOK * 2];
__device__ int   g_tok[NASSIGN];
__device__ float g_gated[(size_t)NASSIGN * E];   // 8 MB
__device__ float g_y[(size_t)NASSIGN * H];       // 8 MB

// ---------------- PTX helpers ----------------
__device__ __forceinline__ uint32_t smem_u32(const void* p) {
    uint32_t a;
    asm("{ .reg .u64 t; cvta.to.shared.u64 t, %1; cvt.u32.u64 %0, t; }" : "=r"(a) : "l"(p));
    return a;
}

__device__ __forceinline__ void ldm_x4(uint32_t (&r)[4], uint32_t addr) {
    asm volatile("ldmatrix.sync.aligned.m8n8.x4.shared.b16 {%0,%1,%2,%3}, [%4];"
                 : "=r"(r[0]), "=r"(r[1]), "=r"(r[2]), "=r"(r[3]) : "r"(addr));
}

__device__ __forceinline__ void mma_bf16(float (&d)[4], const uint32_t (&a)[4],
                                         uint32_t b0, uint32_t b1) {
    asm volatile("mma.sync.aligned.m16n8k16.row.col.f32.bf16.bf16.f32 "
                 "{%0,%1,%2,%3}, {%4,%5,%6,%7}, {%8,%9}, {%0,%1,%2,%3};"
                 : "+f"(d[0]), "+f"(d[1]), "+f"(d[2]), "+f"(d[3])
                 : "r"(a[0]), "r"(a[1]), "r"(a[2]), "r"(a[3]), "r"(b0), "r"(b1));
}

#define STS128(a0, a1, a2, a3, addr) \
    asm volatile("st.shared.v4.b32 [%0], {%1, %2, %3, %4};" \
                 :: "r"(addr), "r"(a0), "r"(a1), "r"(a2), "r"(a3) : "memory")

// row has 8 chunks of 16B: [hi: 0-3 | lo: 4-7]; Swizzle<3,4,3>
__device__ __forceinline__ uint32_t swz_off(int row, int chunk) {
    return (uint32_t)(row * 128 + ((chunk ^ (row & 7)) << 4));
}

// pack (f0,f1) -> bf16x2 hi (f0 in low half) + bf16x2 residual lo
__device__ __forceinline__ void split_pack2(float f0, float f1, uint32_t& hi, uint32_t& lo) {
    uint32_t h;
    asm("cvt.rn.bf16x2.f32 %0, %1, %2;" : "=r"(h) : "f"(f1), "f"(f0));
    float l0 = f0 - __uint_as_float(h << 16);
    float l1 = f1 - __uint_as_float(h & 0xffff0000u);
    uint32_t l;
    asm("cvt.rn.bf16x2.f32 %0, %1, %2;" : "=r"(l) : "f"(l1), "f"(l0));
    hi = h; lo = l;
}

// ---------------- router path ----------------
__global__ void init_kernel() {
    if (threadIdx.x < NEXP) g_counts[threadIdx.x] = 0;
}

__global__ void router_kernel(const float* __restrict__ x,
                              const float* __restrict__ Wg,
                              const float* __restrict__ bg) {
    int t = blockIdx.x * blockDim.y + threadIdx.y;
    int lane = threadIdx.x;
    if (t >= NTOK) return;
    const float* xr = x + (size_t)t * H;
    float logits[NEXP];
#pragma unroll
    for (int e = 0; e < NEXP; e++) {
        const float* wr = Wg + e * H;
        float s = 0.0f;
        for (int h = lane; h < H; h += 32) s += xr[h] * wr[h];
#pragma unroll
        for (int off = 16; off > 0; off >>= 1) s += __shfl_xor_sync(0xffffffffu, s, off);
        logits[e] = s + bg[e];
    }
    if (lane == 0) {
        int i0 = 0; float v0 = logits[0];
#pragma unroll
        for (int e = 1; e < NEXP; e++) if (logits[e] > v0) { v0 = logits[e]; i0 = e; }
        int i1 = -1; float v1 = -INFINITY;
#pragma unroll
        for (int e = 0; e < NEXP; e++) if (e != i0 && logits[e] > v1) { v1 = logits[e]; i1 = e; }
        float r  = expf(v1 - v0);
        float w0 = 1.0f / (1.0f + r);
        g_te[t * 2 + 0] = i0;  g_tw[t * 2 + 0] = w0;
        g_te[t * 2 + 1] = i1;  g_tw[t * 2 + 1] = r * w0;
        atomicAdd(&g_counts[i0], 1);
        atomicAdd(&g_counts[i1], 1);
    }
}

// merged scan + fill: keeps gemm1 as 4th launch for the profiler slot
__global__ void scanfill_kernel() {
    const int t = threadIdx.x;
    if (t == 0) {
        int acc = 0;
#pragma unroll
        for (int e = 0; e < NEXP; e++) { g_off[e] = acc; acc += g_counts[e]; g_fill[e] = 0; }
    }
    __syncthreads();
#pragma unroll
    for (int k = 0; k < 2; k++) {
        int e = g_te[t * 2 + k];
        int pos = atomicAdd(&g_fill[e], 1);
        int idx = g_off[e] + pos;
        g_tok[idx] = t;
        g_slot[t * 2 + k] = idx;
    }
}

// ---------------- shared mma.sync mainloop (128x128 tile, 3-stage) ----------------
// schedule per iter: STS(stage it+1 from regs) -> LDG(regs for it+2) -> compute(stage it) -> bar
__device__ __forceinline__ void gemm_tile(const float4* __restrict__ arow,
                                          const float*  __restrict__ bcol, int ldb,
                                          char* smem, float acc[2][8][4], int kiters) {
    const int tid  = threadIdx.x;
    const int lane = tid & 31;
    const int w    = tid >> 5;
    const int wm   = w & 3;
    const int wn   = w >> 2;
    const int lrow = tid & 127;
    const int half = tid >> 7;        // which 16 of the 32-k chunk this thread loads

    const uint32_t sb = smem_u32(smem);

    const uint32_t sH0 = swz_off(lrow, half * 2);
    const uint32_t sH1 = swz_off(lrow, half * 2 + 1);
    const uint32_t sL0 = swz_off(lrow, 4 + half * 2);
    const uint32_t sL1 = swz_off(lrow, 5 + half * 2);

    const int rA0 = wm * 32 + (lane & 15);
    const int rB0 = wn * 64 + (lane & 7) + ((lane >> 4) << 3);
    const int bkc = (lane >> 3) & 1;
    const int akc = lane >> 4;

    float4 pa[4];
    float  pb[16];

    auto load = [&](int it) {
        const int kb = it * 32 + half * 16;
        if (arow) {
#pragma unroll
            for (int i = 0; i < 4; i++) pa[i] = arow[(kb >> 2) + i];
        } else {
#pragma unroll
            for (int i = 0; i < 4; i++) pa[i] = make_float4(0.f, 0.f, 0.f, 0.f);
        }
#pragma unroll
        for (int j = 0; j < 16; j++) pb[j] = bcol[(size_t)(kb + j) * ldb];
    };

    auto sts = [&](uint32_t stg) {
        uint32_t h[8], l[8];
        split_pack2(pa[0].x, pa[0].y, h[0], l[0]);
        split_pack2(pa[0].z, pa[0].w, h[1], l[1]);
        split_pack2(pa[1].x, pa[1].y, h[2], l[2]);
        split_pack2(pa[1].z, pa[1].w, h[3], l[3]);
        split_pack2(pa[2].x, pa[2].y, h[4], l[4]);
        split_pack2(pa[2].z, pa[2].w, h[5], l[5]);
        split_pack2(pa[3].x, pa[3].y, h[6], l[6]);
        split_pack2(pa[3].z, pa[3].w, h[7], l[7]);
        STS128(h[0], h[1], h[2], h[3], stg + sH0);
        STS128(h[4], h[5], h[6], h[7], stg + sH1);
        STS128(l[0], l[1], l[2], l[3], stg + sL0);
        STS128(l[4], l[5], l[6], l[7], stg + sL1);
#pragma unroll
        for (int p = 0; p < 8; p++) split_pack2(pb[2 * p], pb[2 * p + 1], h[p], l[p]);
        STS128(h[0], h[1], h[2], h[3], stg + B_OFF + sH0);
        STS128(h[4], h[5], h[6], h[7], stg + B_OFF + sH1);
        STS128(l[0], l[1], l[2], l[3], stg + B_OFF + sL0);
        STS128(l[4], l[5], l[6], l[7], stg + B_OFF + sL1);
    };

    auto compute = [&](uint32_t stg) {
#pragma unroll
        for (int s = 0; s < 2; s++) {
            uint32_t ah[2][4], al[2][4];
#pragma unroll
            for (int t = 0; t < 2; t++) {
                int row = rA0 + t * 16;
                int ch  = 2 * s + akc;
                ldm_x4(ah[t], stg + swz_off(row, ch));
                ldm_x4(al[t], stg + swz_off(row, ch + 4));
            }
#pragma unroll
            for (int ug = 0; ug < 4; ug++) {
                int row = rB0 + ug * 16;
                int ch  = 2 * s + bkc;
                uint32_t bh[4], bl[4];
                ldm_x4(bh, stg + B_OFF + swz_off(row, ch));
                ldm_x4(bl, stg + B_OFF + swz_off(row, ch + 4));
#pragma unroll
                for (int t = 0; t < 2; t++) {
#pragma unroll
                    for (int uu = 0; uu < 2; uu++) {
                        mma_bf16(acc[t][ug * 2 + uu], ah[t], bh[uu * 2], bh[uu * 2 + 1]);
                        mma_bf16(acc[t][ug * 2 + uu], ah[t], bl[uu * 2], bl[uu * 2 + 1]);
                        mma_bf16(acc[t][ug * 2 + uu], al[t], bh[uu * 2], bh[uu * 2 + 1]);
                    }
                }
            }
        }
    };

    // prologue: stage0 filled, regs hold chunk 1
    load(0);
    sts(sb);
    load(1);
    __syncthreads();

    uint32_t cur = sb, nxt = sb + STAGE_SZ, spare = sb + 2 * STAGE_SZ;
    for (int it = 0; it < kiters; it++) {
        if (it + 1 < kiters) sts(nxt);        // from regs(it+1), into unused stage
        if (it + 2 < kiters) load(it + 2);    // refill regs; full iter to cover latency
        compute(cur);
        __syncthreads();
        uint32_t t0 = cur; cur = nxt; nxt = spare; spare = t0;
    }
}

// ---------------- GEMM1: X @ Wgu -> clamp/GLU -> g_gated ----------------
__global__ __launch_bounds__(256, 1)
void gemm1_kernel(const float* __restrict__ x,
                  const float* __restrict__ Wgu,
                  const float* __restrict__ bgu) {
    const int e  = blockIdx.z;
    const int ne = g_counts[e];
    const int m0 = blockIdx.y * 128;
    if (m0 >= ne) return;
    const int n0   = blockIdx.x * 128;
    const int base = g_off[e];

    extern __shared__ char smem[];
    const int tid = threadIdx.x, lane = tid & 31, w = tid >> 5;
    const int wm = w & 3, wn = w >> 2;
    const int lrow = tid & 127;

    const int gmL = m0 + lrow;
    const float4* arow = (gmL < ne) ? (const float4*)(x + (size_t)g_tok[base + gmL] * H)
                                    : nullptr;
    const float* bcol = Wgu + (size_t)e * H * E2 + n0 + lrow;

    float acc[2][8][4] = {};
    gemm_tile(arow, bcol, E2, smem, acc, H / 32);

#pragma unroll
    for (int t = 0; t < 2; t++) {
        const int r = wm * 32 + t * 16 + (lane >> 2);
#pragma unroll
        for (int u = 0; u < 8; u++) {
            const int gcol = n0 + wn * 64 + u * 8 + (lane & 3) * 2;
            const float b0 = bgu[e * E2 + gcol];
            const float b1 = bgu[e * E2 + gcol + 1];
#pragma unroll
            for (int hh = 0; hh < 2; hh++) {
                const int gm = m0 + r + hh * 8;
                if (gm < ne) {
                    float gate = acc[t][u][hh * 2]     + b0;
                    float up   = acc[t][u][hh * 2 + 1] + b1;
                    gate = fminf(gate, LIMIT);
                    up   = fminf(fmaxf(up, -LIMIT), LIMIT);
                    float glu = gate / (1.0f + __expf(-ALPHA * gate));
                    g_gated[(size_t)(base + gm) * E + (gcol >> 1)] = (up + 1.0f) * glu;
                }
            }
        }
    }
}

// ---------------- GEMM2: gated @ Wd -> per-assignment rows g_y ----------------
__global__ __launch_bounds__(256, 1)
void gemm2_kernel(const float* __restrict__ Wd,
                  const float* __restrict__ bd) {
    const int e  = blockIdx.z;
    const int ne = g_counts[e];
    const int m0 = blockIdx.y * 128;
    if (m0 >= ne) return;
    const int n0   = blockIdx.x * 128;
    const int base = g_off[e];

    extern __shared__ char smem[];
    const int tid = threadIdx.x, lane = tid & 31, w = tid >> 5;
    const int wm = w & 3, wn = w >> 2;
    const int lrow = tid & 127;

    const int gmL = m0 + lrow;
    const float4* arow = (gmL < ne) ? (const float4*)(g_gated + (size_t)(base + gmL) * E)
                                    : nullptr;
    const float* bcol = Wd + (size_t)e * E * H + n0 + lrow;

    float acc[2][8][4] = {};
    gemm_tile(arow, bcol, H, smem, acc, E / 32);

#pragma unroll
    for (int t = 0; t < 2; t++) {
        const int r = wm * 32 + t * 16 + (lane >> 2);
#pragma unroll
        for (int u = 0; u < 8; u++) {
            const int col = n0 + wn * 64 + u * 8 + (lane & 3) * 2;
            const float b0 = bd[e * H + col];
            const float b1 = bd[e * H + col + 1];
#pragma unroll
            for (int hh = 0; hh < 2; hh++) {
                const int gm = m0 + r + hh * 8;
                if (gm < ne) {
                    float2 v = make_float2(acc[t][u][hh * 2] + b0,
                                           acc[t][u][hh * 2 + 1] + b1);
                    *(float2*)&g_y[(size_t)(base + gm) * H + col] = v;
                }
            }
        }
    }
}

// ---------------- combine: out[t] = w0*y[slot0] + w1*y[slot1] ----------------
__global__ void combine_kernel(float* __restrict__ out) {
    const int i = blockIdx.x * 256 + threadIdx.x;   // over NTOK*H/4
    const int t = i >> 8;
    const int c = i & 255;
    const int s0 = g_slot[t * 2], s1 = g_slot[t * 2 + 1];
    const float w0 = g_tw[t * 2], w1 = g_tw[t * 2 + 1];
    const float4 a = ((const float4*)(g_y + (size_t)s0 * H))[c];
    const float4 b = ((const float4*)(g_y + (size_t)s1 * H))[c];
    float4 o;
    o.x = w0 * a.x + w1 * b.x;
    o.y = w0 * a.y + w1 * b.y;
    o.z = w0 * a.z + w1 * b.z;
    o.w = w0 * a.w + w1 * b.w;
    ((float4*)out)[i] = o;
}

// ---------------- launch ----------------
extern "C" void kernel_launch(void* const* d_in, const int* in_sizes, int n_in,
                              void* d_out, int out_size) {
    (void)in_sizes; (void)n_in; (void)out_size;
    const float* x   = (const float*)d_in[0];
    const float* Wg  = (const float*)d_in[1];
    const float* bg  = (const float*)d_in[2];
    const float* Wgu = (const float*)d_in[3];
    const float* bgu = (const float*)d_in[4];
    const float* Wd  = (const float*)d_in[5];
    const float* bd  = (const float*)d_in[6];
    float* out = (float*)d_out;

    static bool attr_set = false;
    if (!attr_set) {
        cudaFuncSetAttribute(gemm1_kernel, cudaFuncAttributeMaxDynamicSharedMemorySize, SMEM_TOTAL);
        cudaFuncSetAttribute(gemm2_kernel, cudaFuncAttributeMaxDynamicSharedMemorySize, SMEM_TOTAL);
        attr_set = true;
    }

    // gemm1 is deliberately the 4th launch: ncu's fixed skip-count profiles it.
    init_kernel<<<1, 32>>>();
    router_kernel<<<NTOK / 8, dim3(32, 8)>>>(x, Wg, bg);
    scanfill_kernel<<<1, 1024>>>();
    gemm1_kernel<<<dim3(E2 / 128, 8, NEXP), 256, SMEM_TOTAL>>>(x, Wgu, bgu);
    gemm2_kernel<<<dim3(H / 128, 8, NEXP), 256, SMEM_TOTAL>>>(Wd, bd);
    combine_kernel<<<NTOK * H / 4 / 256, 256>>>(out);
}